// round 1
// baseline (speedup 1.0000x reference)
#include <cuda_runtime.h>
#include <math.h>

#define BN_EPS 1e-5f
#define ATT_SCALE 0.25f   // 16^-0.5

// ---------------- scratch (static device buffers; no allocations) ----------
__device__ float g_kv   [64u*384u*784u];  // kv conv output  [b][o=384][n=784]
__device__ float g_q    [64u*128u*196u];  // q  conv output  [b][o=128][n=196]
__device__ float g_biasT[ 8u*784u*196u];  // bias transposed [h][m][n]
__device__ float g_att  [64u*256u*196u];  // hardswish(attn out) [b][c=256][n=196]

__device__ __forceinline__ float hardswish(float x) {
    float t = fminf(fmaxf(x + 3.f, 0.f), 6.f);
    return x * t * (1.f / 6.f);
}

// ---------------- bias gather: biasT[h][m][n] = ab[h][idxs[n][m]] ----------
__global__ void bias_gather_kernel(const float* __restrict__ ab,
                                   const int*   __restrict__ idxs,
                                   int n_off)
{
    int m = blockIdx.x;       // 0..783
    int h = blockIdx.y;       // 0..7
    int n = threadIdx.x;      // 0..195
    int idx = idxs[n * 784 + m];
    g_biasT[((size_t)h * 784 + m) * 196 + n] = ab[h * n_off + idx];
}

// ---------------- tiled SGEMM + BN + hardswish ------------------------------
// Y[b][o][n] = hardswish( (sum_c X[b][c][col(n)] * W[o][c] - mu[o])*scale[o] + beta[o] )
// STRIDED=true maps n (14x14 grid) -> gn = 2*(n/14)*28 + 2*(n%14) (the ::2,::2 subsample)
template<bool STRIDED>
__global__ void __launch_bounds__(256)
conv_bn_hsw_kernel(const float* __restrict__ X, int x_batch_stride, int ldx,
                   const float* __restrict__ W, int C,
                   const float* __restrict__ gam, const float* __restrict__ bet,
                   const float* __restrict__ mu,  const float* __restrict__ var,
                   float* __restrict__ Y, int O, int Ncols)
{
    __shared__ float As[16][65];
    __shared__ float Bs[16][64];

    const int b  = blockIdx.z;
    const float* Xb = X + (size_t)b * x_batch_stride;
    float*       Yb = Y + (size_t)b * O * Ncols;
    const int o0 = blockIdx.x * 64;
    const int n0 = blockIdx.y * 64;
    const int t  = threadIdx.x;
    const int tx = t & 15, ty = t >> 4;

    const int arow = t >> 2, aseg = t & 3;          // A loader: 64 rows x 4 float4 segs
    const int brow = t >> 4, bcol = (t & 15) * 4;   // B loader: 16 rows x 16 quads

    float acc[4][4] = {};

    for (int c0 = 0; c0 < C; c0 += 16) {
        // --- load A tile (weights, always in-bounds: O,C multiples of 64/16)
        float4 av = *reinterpret_cast<const float4*>(&W[(o0 + arow) * C + c0 + aseg * 4]);
        As[aseg * 4 + 0][arow] = av.x;
        As[aseg * 4 + 1][arow] = av.y;
        As[aseg * 4 + 2][arow] = av.z;
        As[aseg * 4 + 3][arow] = av.w;

        // --- load B tile
        int c = c0 + brow;
        if (!STRIDED && (n0 + 64 <= Ncols)) {
            float4 bv = *reinterpret_cast<const float4*>(&Xb[(size_t)c * ldx + n0 + bcol]);
            *reinterpret_cast<float4*>(&Bs[brow][bcol]) = bv;
        } else {
            #pragma unroll
            for (int j = 0; j < 4; j++) {
                int n = n0 + bcol + j;
                float val = 0.f;
                if (n < Ncols) {
                    int gn = STRIDED ? (2 * (n / 14) * 28 + 2 * (n % 14)) : n;
                    val = Xb[(size_t)c * ldx + gn];
                }
                Bs[brow][bcol + j] = val;
            }
        }
        __syncthreads();

        #pragma unroll
        for (int kk = 0; kk < 16; kk++) {
            float a[4], bb[4];
            #pragma unroll
            for (int i = 0; i < 4; i++) a[i]  = As[kk][ty * 4 + i];
            #pragma unroll
            for (int j = 0; j < 4; j++) bb[j] = Bs[kk][tx * 4 + j];
            #pragma unroll
            for (int i = 0; i < 4; i++)
                #pragma unroll
                for (int j = 0; j < 4; j++)
                    acc[i][j] = fmaf(a[i], bb[j], acc[i][j]);
        }
        __syncthreads();
    }

    // --- epilogue: BN + hardswish
    #pragma unroll
    for (int i = 0; i < 4; i++) {
        int o = o0 + ty * 4 + i;
        float sc = gam[o] * rsqrtf(var[o] + BN_EPS);
        float mm = mu[o], bt = bet[o];
        #pragma unroll
        for (int j = 0; j < 4; j++) {
            int n = n0 + tx * 4 + j;
            if (n < Ncols) {
                float y = (acc[i][j] - mm) * sc + bt;
                Yb[(size_t)o * Ncols + n] = hardswish(y);
            }
        }
    }
}

// ---------------- fused attention (online softmax) --------------------------
// one block per (b,h); thread n owns query row n (196 active of 224)
__global__ void __launch_bounds__(224)
attention_kernel()
{
    const int bh = blockIdx.x;
    const int b = bh >> 3, h = bh & 7;
    const int t = threadIdx.x;

    __shared__ float ks[16][16];   // k[d][mm]
    __shared__ float vs[32][16];   // v[d][mm]

    const float* kvb    = g_kv    + ((size_t)b * 384 + (size_t)h * 48) * 784;
    const float* biasTh = g_biasT + (size_t)h * 784 * 196;

    const int n = t;
    const bool active = (n < 196);

    float qr[16];
    float out[32];
    float run_max = -1e30f, run_l = 0.f;

    if (active) {
        #pragma unroll
        for (int d = 0; d < 16; d++)
            qr[d] = g_q[(((size_t)b * 128) + h * 16 + d) * 196 + n] * ATT_SCALE;
    }
    #pragma unroll
    for (int d = 0; d < 32; d++) out[d] = 0.f;

    for (int m0 = 0; m0 < 784; m0 += 16) {
        // cooperative load of K/V chunk (768 floats, 224 threads)
        for (int idx = t; idx < 768; idx += 224) {
            if (idx < 256) {
                int d = idx >> 4, mm = idx & 15;
                ks[d][mm] = kvb[(size_t)d * 784 + m0 + mm];
            } else {
                int q2 = idx - 256;
                int d = q2 >> 4, mm = q2 & 15;
                vs[d][mm] = kvb[(size_t)(16 + d) * 784 + m0 + mm];
            }
        }
        __syncthreads();

        if (active) {
            float s[16];
            float cmax = run_max;
            #pragma unroll
            for (int mm = 0; mm < 16; mm++) {
                float acc = biasTh[(size_t)(m0 + mm) * 196 + n];
                #pragma unroll
                for (int d = 0; d < 16; d++)
                    acc = fmaf(qr[d], ks[d][mm], acc);
                s[mm] = acc;
                cmax = fmaxf(cmax, acc);
            }
            float alpha = __expf(run_max - cmax);
            run_l *= alpha;
            #pragma unroll
            for (int d = 0; d < 32; d++) out[d] *= alpha;
            #pragma unroll
            for (int mm = 0; mm < 16; mm++) {
                float p = __expf(s[mm] - cmax);
                run_l += p;
                #pragma unroll
                for (int d = 0; d < 32; d++)
                    out[d] = fmaf(p, vs[d][mm], out[d]);
            }
            run_max = cmax;
        }
        __syncthreads();
    }

    if (active) {
        float inv = 1.f / run_l;
        float* ob = g_att + (((size_t)b * 256) + h * 32) * 196 + n;
        #pragma unroll
        for (int d = 0; d < 32; d++)
            ob[(size_t)d * 196] = hardswish(out[d] * inv);  // pre-proj hardswish fused here
    }
}

// ---------------- launch -----------------------------------------------------
extern "C" void kernel_launch(void* const* d_in, const int* in_sizes, int n_in,
                              void* d_out, int out_size)
{
    const float* x      = (const float*)d_in[0];
    const float* kv_w   = (const float*)d_in[1];
    const float* kv_g   = (const float*)d_in[2];
    const float* kv_b   = (const float*)d_in[3];
    const float* kv_m   = (const float*)d_in[4];
    const float* kv_v   = (const float*)d_in[5];
    const float* q_w    = (const float*)d_in[6];
    const float* q_g    = (const float*)d_in[7];
    const float* q_b    = (const float*)d_in[8];
    const float* q_m    = (const float*)d_in[9];
    const float* q_v    = (const float*)d_in[10];
    const float* proj_w = (const float*)d_in[11];
    const float* proj_g = (const float*)d_in[12];
    const float* proj_b = (const float*)d_in[13];
    const float* proj_m = (const float*)d_in[14];
    const float* proj_v = (const float*)d_in[15];
    const float* ab     = (const float*)d_in[16];
    const int*   idxs   = (const int*)  d_in[17];
    const int n_off = in_sizes[16] / 8;

    float* out = (float*)d_out;

    float *p_kv, *p_q, *p_att;
    cudaGetSymbolAddress((void**)&p_kv,  g_kv);
    cudaGetSymbolAddress((void**)&p_q,   g_q);
    cudaGetSymbolAddress((void**)&p_att, g_att);

    // 1) bias table (transposed for coalesced attention reads)
    bias_gather_kernel<<<dim3(784, 8), 196>>>(ab, idxs, n_off);

    // 2) kv = conv_bn_hsw(x, kv_w)   -> g_kv [64][384][784]
    conv_bn_hsw_kernel<false><<<dim3(6, 13, 64), 256>>>(
        x, 256 * 784, 784, kv_w, 256, kv_g, kv_b, kv_m, kv_v, p_kv, 384, 784);

    // 3) q = conv_bn_hsw(x[::2,::2], q_w) -> g_q [64][128][196]
    conv_bn_hsw_kernel<true><<<dim3(2, 4, 64), 256>>>(
        x, 256 * 784, 784, q_w, 256, q_g, q_b, q_m, q_v, p_q, 128, 196);

    // 4) fused attention (QK^T*scale + bias, softmax, @V, hardswish) -> g_att
    attention_kernel<<<512, 224>>>();

    // 5) proj = conv_bn_hsw(g_att, proj_w) -> d_out [64][512][196]
    conv_bn_hsw_kernel<false><<<dim3(8, 4, 64), 256>>>(
        p_att, 256 * 196, 196, proj_w, 256, proj_g, proj_b, proj_m, proj_v, out, 512, 196);
}

// round 2
// speedup vs baseline: 1.5138x; 1.5138x over previous
#include <cuda_runtime.h>
#include <math.h>

#define BN_EPS 1e-5f
#define ATT_SCALE 0.25f   // 16^-0.5

// ---------------- scratch (static device buffers; no allocations) ----------
__device__ float g_kv   [64u*384u*784u];  // kv conv output  [b][o=384][n=784]
__device__ float g_q    [64u*128u*196u];  // q  conv output  [b][o=128][n=196]
__device__ float g_biasT[ 8u*784u*196u];  // bias transposed [h][m][n]
__device__ float g_att  [64u*256u*196u];  // hardswish(attn out) [b][c=256][n=196]

__device__ __forceinline__ float hardswish(float x) {
    float t = fminf(fmaxf(x + 3.f, 0.f), 6.f);
    return x * t * (1.f / 6.f);
}

// ---------------- bias gather: biasT[h][m][n] = ab[h][idxs[n][m]] ----------
__global__ void bias_gather_kernel(const float* __restrict__ ab,
                                   const int*   __restrict__ idxs,
                                   int n_off)
{
    int m = blockIdx.x;       // 0..783
    int h = blockIdx.y;       // 0..7
    int n = threadIdx.x;      // 0..195
    int idx = idxs[n * 784 + m];
    g_biasT[((size_t)h * 784 + m) * 196 + n] = ab[h * n_off + idx];
}

// ---------------- tiled SGEMM + BN + hardswish ------------------------------
template<bool STRIDED>
__global__ void __launch_bounds__(256)
conv_bn_hsw_kernel(const float* __restrict__ X, int x_batch_stride, int ldx,
                   const float* __restrict__ W, int C,
                   const float* __restrict__ gam, const float* __restrict__ bet,
                   const float* __restrict__ mu,  const float* __restrict__ var,
                   float* __restrict__ Y, int O, int Ncols)
{
    __shared__ float As[16][65];
    __shared__ float Bs[16][64];

    const int b  = blockIdx.z;
    const float* Xb = X + (size_t)b * x_batch_stride;
    float*       Yb = Y + (size_t)b * O * Ncols;
    const int o0 = blockIdx.x * 64;
    const int n0 = blockIdx.y * 64;
    const int t  = threadIdx.x;
    const int tx = t & 15, ty = t >> 4;

    const int arow = t >> 2, aseg = t & 3;
    const int brow = t >> 4, bcol = (t & 15) * 4;

    float acc[4][4] = {};

    for (int c0 = 0; c0 < C; c0 += 16) {
        float4 av = *reinterpret_cast<const float4*>(&W[(o0 + arow) * C + c0 + aseg * 4]);
        As[aseg * 4 + 0][arow] = av.x;
        As[aseg * 4 + 1][arow] = av.y;
        As[aseg * 4 + 2][arow] = av.z;
        As[aseg * 4 + 3][arow] = av.w;

        int c = c0 + brow;
        if (!STRIDED && (n0 + 64 <= Ncols)) {
            float4 bv = *reinterpret_cast<const float4*>(&Xb[(size_t)c * ldx + n0 + bcol]);
            *reinterpret_cast<float4*>(&Bs[brow][bcol]) = bv;
        } else {
            #pragma unroll
            for (int j = 0; j < 4; j++) {
                int n = n0 + bcol + j;
                float val = 0.f;
                if (n < Ncols) {
                    int gn = STRIDED ? (2 * (n / 14) * 28 + 2 * (n % 14)) : n;
                    val = Xb[(size_t)c * ldx + gn];
                }
                Bs[brow][bcol + j] = val;
            }
        }
        __syncthreads();

        #pragma unroll
        for (int kk = 0; kk < 16; kk++) {
            float a[4], bb[4];
            #pragma unroll
            for (int i = 0; i < 4; i++) a[i]  = As[kk][ty * 4 + i];
            #pragma unroll
            for (int j = 0; j < 4; j++) bb[j] = Bs[kk][tx * 4 + j];
            #pragma unroll
            for (int i = 0; i < 4; i++)
                #pragma unroll
                for (int j = 0; j < 4; j++)
                    acc[i][j] = fmaf(a[i], bb[j], acc[i][j]);
        }
        __syncthreads();
    }

    #pragma unroll
    for (int i = 0; i < 4; i++) {
        int o = o0 + ty * 4 + i;
        float sc = gam[o] * rsqrtf(var[o] + BN_EPS);
        float mm = mu[o], bt = bet[o];
        #pragma unroll
        for (int j = 0; j < 4; j++) {
            int n = n0 + tx * 4 + j;
            if (n < Ncols) {
                float y = (acc[i][j] - mm) * sc + bt;
                Yb[(size_t)o * Ncols + n] = hardswish(y);
            }
        }
    }
}

// ---------------- fused attention (online softmax, float4 smem) -------------
// one block per (b,h); thread n owns query row n (196 active of 224)
// smem tile transposed to [mm][d] so inner loops read float4 broadcasts.
__global__ void __launch_bounds__(224, 2)
attention_kernel()
{
    const int bh = blockIdx.x;
    const int b = bh >> 3, h = bh & 7;
    const int t = threadIdx.x;

    // [mm][d]: d 0..15 = K, d 16..47 = V. Row stride 52 floats (208B, 16B-aligned)
    __shared__ float kvs[16][52];

    const float* kvb    = g_kv    + ((size_t)b * 384 + (size_t)h * 48) * 784;
    const float* biasTh = g_biasT + (size_t)h * 784 * 196;

    const int n = t;
    const bool active = (n < 196);

    float4 q4[4];
    float4 o4[8];
    float run_max = -1e30f, run_l = 0.f;

    if (active) {
        #pragma unroll
        for (int i = 0; i < 4; i++) {
            q4[i].x = g_q[(((size_t)b * 128) + h * 16 + 4*i + 0) * 196 + n] * ATT_SCALE;
            q4[i].y = g_q[(((size_t)b * 128) + h * 16 + 4*i + 1) * 196 + n] * ATT_SCALE;
            q4[i].z = g_q[(((size_t)b * 128) + h * 16 + 4*i + 2) * 196 + n] * ATT_SCALE;
            q4[i].w = g_q[(((size_t)b * 128) + h * 16 + 4*i + 3) * 196 + n] * ATT_SCALE;
        }
    }
    #pragma unroll
    for (int j = 0; j < 8; j++) o4[j] = make_float4(0.f, 0.f, 0.f, 0.f);

    for (int m0 = 0; m0 < 784; m0 += 16) {
        // cooperative transposed load of K/V chunk (768 floats, 224 threads)
        #pragma unroll
        for (int it = 0; it < 4; it++) {
            int idx = t + it * 224;
            if (idx < 768) {
                int d = idx >> 4, mm = idx & 15;
                kvs[mm][d] = kvb[(size_t)d * 784 + m0 + mm];
            }
        }
        __syncthreads();

        if (active) {
            float s[16];
            // prefetch bias (independent LDGs, coalesced over n)
            #pragma unroll
            for (int mm = 0; mm < 16; mm++)
                s[mm] = biasTh[(size_t)(m0 + mm) * 196 + n];

            float cmax = run_max;
            #pragma unroll
            for (int mm = 0; mm < 16; mm++) {
                const float4* kr = reinterpret_cast<const float4*>(&kvs[mm][0]);
                float acc = s[mm];
                #pragma unroll
                for (int i = 0; i < 4; i++) {
                    float4 kk = kr[i];
                    acc = fmaf(q4[i].x, kk.x, acc);
                    acc = fmaf(q4[i].y, kk.y, acc);
                    acc = fmaf(q4[i].z, kk.z, acc);
                    acc = fmaf(q4[i].w, kk.w, acc);
                }
                s[mm] = acc;
                cmax = fmaxf(cmax, acc);
            }

            float alpha = __expf(run_max - cmax);
            run_l *= alpha;
            #pragma unroll
            for (int j = 0; j < 8; j++) {
                o4[j].x *= alpha; o4[j].y *= alpha;
                o4[j].z *= alpha; o4[j].w *= alpha;
            }
            #pragma unroll
            for (int mm = 0; mm < 16; mm++) {
                float p = __expf(s[mm] - cmax);
                run_l += p;
                const float4* vr = reinterpret_cast<const float4*>(&kvs[mm][16]);
                #pragma unroll
                for (int j = 0; j < 8; j++) {
                    float4 vv = vr[j];
                    o4[j].x = fmaf(p, vv.x, o4[j].x);
                    o4[j].y = fmaf(p, vv.y, o4[j].y);
                    o4[j].z = fmaf(p, vv.z, o4[j].z);
                    o4[j].w = fmaf(p, vv.w, o4[j].w);
                }
            }
            run_max = cmax;
        }
        __syncthreads();
    }

    if (active) {
        float inv = 1.f / run_l;
        float* ob = g_att + (((size_t)b * 256) + h * 32) * 196 + n;
        #pragma unroll
        for (int j = 0; j < 8; j++) {
            ob[(size_t)(4*j + 0) * 196] = hardswish(o4[j].x * inv);
            ob[(size_t)(4*j + 1) * 196] = hardswish(o4[j].y * inv);
            ob[(size_t)(4*j + 2) * 196] = hardswish(o4[j].z * inv);
            ob[(size_t)(4*j + 3) * 196] = hardswish(o4[j].w * inv);
        }
    }
}

// ---------------- launch -----------------------------------------------------
extern "C" void kernel_launch(void* const* d_in, const int* in_sizes, int n_in,
                              void* d_out, int out_size)
{
    const float* x      = (const float*)d_in[0];
    const float* kv_w   = (const float*)d_in[1];
    const float* kv_g   = (const float*)d_in[2];
    const float* kv_b   = (const float*)d_in[3];
    const float* kv_m   = (const float*)d_in[4];
    const float* kv_v   = (const float*)d_in[5];
    const float* q_w    = (const float*)d_in[6];
    const float* q_g    = (const float*)d_in[7];
    const float* q_b    = (const float*)d_in[8];
    const float* q_m    = (const float*)d_in[9];
    const float* q_v    = (const float*)d_in[10];
    const float* proj_w = (const float*)d_in[11];
    const float* proj_g = (const float*)d_in[12];
    const float* proj_b = (const float*)d_in[13];
    const float* proj_m = (const float*)d_in[14];
    const float* proj_v = (const float*)d_in[15];
    const float* ab     = (const float*)d_in[16];
    const int*   idxs   = (const int*)  d_in[17];
    const int n_off = in_sizes[16] / 8;

    float* out = (float*)d_out;

    float *p_kv, *p_q, *p_att;
    cudaGetSymbolAddress((void**)&p_kv,  g_kv);
    cudaGetSymbolAddress((void**)&p_q,   g_q);
    cudaGetSymbolAddress((void**)&p_att, g_att);

    // 1) bias table (transposed for coalesced attention reads)
    bias_gather_kernel<<<dim3(784, 8), 196>>>(ab, idxs, n_off);

    // 2) kv = conv_bn_hsw(x, kv_w)   -> g_kv [64][384][784]
    conv_bn_hsw_kernel<false><<<dim3(6, 13, 64), 256>>>(
        x, 256 * 784, 784, kv_w, 256, kv_g, kv_b, kv_m, kv_v, p_kv, 384, 784);

    // 3) q = conv_bn_hsw(x[::2,::2], q_w) -> g_q [64][128][196]
    conv_bn_hsw_kernel<true><<<dim3(2, 4, 64), 256>>>(
        x, 256 * 784, 784, q_w, 256, q_g, q_b, q_m, q_v, p_q, 128, 196);

    // 4) fused attention (QK^T*scale + bias, softmax, @V, hardswish) -> g_att
    attention_kernel<<<512, 224>>>();

    // 5) proj = conv_bn_hsw(g_att, proj_w) -> d_out [64][512][196]
    conv_bn_hsw_kernel<false><<<dim3(8, 4, 64), 256>>>(
        p_att, 256 * 196, 196, proj_w, 256, proj_g, proj_b, proj_m, proj_v, out, 512, 196);
}

// round 3
// speedup vs baseline: 1.5399x; 1.0172x over previous
#include <cuda_runtime.h>
#include <math.h>
#include <stdint.h>

#define BN_EPS 1e-5f
#define ATT_SCALE 0.25f   // 16^-0.5

// ---------------- scratch (static device buffers; no allocations) ----------
__device__ float g_kv   [64u*384u*784u];  // kv conv output  [b][o=384][n=784]
__device__ float g_q    [64u*128u*196u];  // q  conv output  [b][o=128][n=196]
__device__ float g_biasT[ 8u*784u*196u];  // bias transposed [h][m][n]
__device__ float g_att  [64u*256u*196u];  // hardswish(attn out) [b][c=256][n=196]

__device__ __forceinline__ float hardswish(float x) {
    float t = fminf(fmaxf(x + 3.f, 0.f), 6.f);
    return x * t * (1.f / 6.f);
}

__device__ __forceinline__ uint32_t f2tf32(float x) {
    uint32_t r;
    asm("cvt.rna.tf32.f32 %0, %1;" : "=r"(r) : "f"(x));
    return r;
}

// ---------------- bias gather: biasT[h][m][n] = ab[h][idxs[n][m]] ----------
__global__ void bias_gather_kernel(const float* __restrict__ ab,
                                   const int*   __restrict__ idxs,
                                   int n_off)
{
    int m = blockIdx.x;       // 0..783
    int h = blockIdx.y;       // 0..7
    int n = threadIdx.x;      // 0..195
    int idx = idxs[n * 784 + m];
    g_biasT[((size_t)h * 784 + m) * 196 + n] = ab[h * n_off + idx];
}

// ---------------- TF32 tensor-core GEMM + BN + hardswish --------------------
// Y[b][o][n] = hardswish( (sum_c W[o][c]*X[b][c][col(n)] - mu[o])*scale[o] + beta[o] )
// Block tile 128(O) x 64(N), K-slab 16, 8 warps (warp tile 64x16), tf32 mma m16n8k8.
// STRIDED=true: n -> gn = 2*(n/14)*28 + 2*(n%14)  (::2,::2 subsample of 28x28)
template<bool STRIDED>
__global__ void __launch_bounds__(256, 2)
conv_bn_hsw_tc_kernel(const float* __restrict__ X, int x_batch_stride, int ldx,
                      const float* __restrict__ W, int C,
                      const float* __restrict__ gam, const float* __restrict__ bet,
                      const float* __restrict__ mu,  const float* __restrict__ var,
                      float* __restrict__ Y, int O, int Ncols)
{
    __shared__ uint32_t As[128][20];  // A[row 128][k 16] tf32, pitch 20 (conflict-free frags)
    __shared__ uint32_t Bs[64][20];   // B stored transposed: Bs[n][k] tf32, pitch 20

    const int b  = blockIdx.z;
    const float* Xb = X + (size_t)b * x_batch_stride;
    float*       Yb = Y + (size_t)b * O * Ncols;
    const int o0 = blockIdx.x * 128;
    const int n0 = blockIdx.y * 64;
    const int t  = threadIdx.x;

    const int warp = t >> 5;
    const int lane = t & 31;
    const int g    = lane >> 2;     // groupID 0..7
    const int t4   = lane & 3;      // threadID_in_group 0..3
    const int wm   = warp >> 2;     // 0..1  (M warp coord)
    const int wn   = warp & 3;      // 0..3  (N warp coord)
    const int mrow0 = wm * 64;      // warp M base within block
    const int ncol0 = wn * 16;      // warp N base within block

    // A loader: 512 float4 quads (128 rows x 4 segs), 2 per thread
    // B loader: 1024 floats (16 k x 64 n), 4 per thread
    float acc[4][2][4];
    #pragma unroll
    for (int i = 0; i < 4; i++)
        #pragma unroll
        for (int j = 0; j < 2; j++)
            #pragma unroll
            for (int e = 0; e < 4; e++) acc[i][j][e] = 0.f;

    for (int c0 = 0; c0 < C; c0 += 16) {
        // ---- load A slab: W[o0..o0+127][c0..c0+15]  (always in-bounds)
        #pragma unroll
        for (int r = 0; r < 2; r++) {
            int q = t + r * 256;            // 0..511
            int row = q >> 2, seg = q & 3;
            float4 av = *reinterpret_cast<const float4*>(&W[(o0 + row) * C + c0 + seg * 4]);
            As[row][seg * 4 + 0] = f2tf32(av.x);
            As[row][seg * 4 + 1] = f2tf32(av.y);
            As[row][seg * 4 + 2] = f2tf32(av.z);
            As[row][seg * 4 + 3] = f2tf32(av.w);
        }
        // ---- load B slab: X[c0..c0+15][n0..n0+63] -> Bs[n][k]
        #pragma unroll
        for (int r = 0; r < 4; r++) {
            int i = t + r * 256;            // 0..1023
            int k = i >> 6, n = i & 63;
            int nn = n0 + n;
            float val = 0.f;
            if (nn < Ncols) {
                int gn = STRIDED ? (2 * (nn / 14) * 28 + 2 * (nn % 14)) : nn;
                val = Xb[(size_t)(c0 + k) * ldx + gn];
            }
            Bs[n][k] = f2tf32(val);
        }
        __syncthreads();

        // ---- 2 k-steps of 8
        #pragma unroll
        for (int ks = 0; ks < 16; ks += 8) {
            uint32_t a[4][4];
            #pragma unroll
            for (int mf = 0; mf < 4; mf++) {
                int rb = mrow0 + mf * 16;
                a[mf][0] = As[rb + g    ][ks + t4    ];
                a[mf][1] = As[rb + g + 8][ks + t4    ];
                a[mf][2] = As[rb + g    ][ks + t4 + 4];
                a[mf][3] = As[rb + g + 8][ks + t4 + 4];
            }
            uint32_t bfr[2][2];
            #pragma unroll
            for (int nf = 0; nf < 2; nf++) {
                int cb = ncol0 + nf * 8;
                bfr[nf][0] = Bs[cb + g][ks + t4    ];
                bfr[nf][1] = Bs[cb + g][ks + t4 + 4];
            }
            #pragma unroll
            for (int mf = 0; mf < 4; mf++)
                #pragma unroll
                for (int nf = 0; nf < 2; nf++) {
                    asm volatile(
                        "mma.sync.aligned.m16n8k8.row.col.f32.tf32.tf32.f32 "
                        "{%0,%1,%2,%3}, {%4,%5,%6,%7}, {%8,%9}, {%0,%1,%2,%3};"
                        : "+f"(acc[mf][nf][0]), "+f"(acc[mf][nf][1]),
                          "+f"(acc[mf][nf][2]), "+f"(acc[mf][nf][3])
                        : "r"(a[mf][0]), "r"(a[mf][1]), "r"(a[mf][2]), "r"(a[mf][3]),
                          "r"(bfr[nf][0]), "r"(bfr[nf][1]));
                }
        }
        __syncthreads();
    }

    // ---- epilogue: BN + hardswish
    #pragma unroll
    for (int mf = 0; mf < 4; mf++) {
        #pragma unroll
        for (int half = 0; half < 2; half++) {
            int o = o0 + mrow0 + mf * 16 + g + half * 8;
            float sc = gam[o] * rsqrtf(var[o] + BN_EPS);
            float mm = mu[o], bt = bet[o];
            #pragma unroll
            for (int nf = 0; nf < 2; nf++) {
                #pragma unroll
                for (int e = 0; e < 2; e++) {
                    int n = n0 + ncol0 + nf * 8 + t4 * 2 + e;
                    if (n < Ncols) {
                        float y = (acc[mf][nf][half * 2 + e] - mm) * sc + bt;
                        Yb[(size_t)o * Ncols + n] = hardswish(y);
                    }
                }
            }
        }
    }
}

// ---------------- fused attention (online softmax, float4 smem) -------------
__global__ void __launch_bounds__(224, 2)
attention_kernel()
{
    const int bh = blockIdx.x;
    const int b = bh >> 3, h = bh & 7;
    const int t = threadIdx.x;

    __shared__ float kvs[16][52];   // [mm][d]: d 0..15 = K, 16..47 = V

    const float* kvb    = g_kv    + ((size_t)b * 384 + (size_t)h * 48) * 784;
    const float* biasTh = g_biasT + (size_t)h * 784 * 196;

    const int n = t;
    const bool active = (n < 196);

    float4 q4[4];
    float4 o4[8];
    float run_max = -1e30f, run_l = 0.f;

    if (active) {
        #pragma unroll
        for (int i = 0; i < 4; i++) {
            q4[i].x = g_q[(((size_t)b * 128) + h * 16 + 4*i + 0) * 196 + n] * ATT_SCALE;
            q4[i].y = g_q[(((size_t)b * 128) + h * 16 + 4*i + 1) * 196 + n] * ATT_SCALE;
            q4[i].z = g_q[(((size_t)b * 128) + h * 16 + 4*i + 2) * 196 + n] * ATT_SCALE;
            q4[i].w = g_q[(((size_t)b * 128) + h * 16 + 4*i + 3) * 196 + n] * ATT_SCALE;
        }
    }
    #pragma unroll
    for (int j = 0; j < 8; j++) o4[j] = make_float4(0.f, 0.f, 0.f, 0.f);

    for (int m0 = 0; m0 < 784; m0 += 16) {
        #pragma unroll
        for (int it = 0; it < 4; it++) {
            int idx = t + it * 224;
            if (idx < 768) {
                int d = idx >> 4, mm = idx & 15;
                kvs[mm][d] = kvb[(size_t)d * 784 + m0 + mm];
            }
        }
        __syncthreads();

        if (active) {
            float s[16];
            #pragma unroll
            for (int mm = 0; mm < 16; mm++)
                s[mm] = biasTh[(size_t)(m0 + mm) * 196 + n];

            float cmax = run_max;
            #pragma unroll
            for (int mm = 0; mm < 16; mm++) {
                const float4* kr = reinterpret_cast<const float4*>(&kvs[mm][0]);
                float acc = s[mm];
                #pragma unroll
                for (int i = 0; i < 4; i++) {
                    float4 kk = kr[i];
                    acc = fmaf(q4[i].x, kk.x, acc);
                    acc = fmaf(q4[i].y, kk.y, acc);
                    acc = fmaf(q4[i].z, kk.z, acc);
                    acc = fmaf(q4[i].w, kk.w, acc);
                }
                s[mm] = acc;
                cmax = fmaxf(cmax, acc);
            }

            float alpha = __expf(run_max - cmax);
            run_l *= alpha;
            #pragma unroll
            for (int j = 0; j < 8; j++) {
                o4[j].x *= alpha; o4[j].y *= alpha;
                o4[j].z *= alpha; o4[j].w *= alpha;
            }
            #pragma unroll
            for (int mm = 0; mm < 16; mm++) {
                float p = __expf(s[mm] - cmax);
                run_l += p;
                const float4* vr = reinterpret_cast<const float4*>(&kvs[mm][16]);
                #pragma unroll
                for (int j = 0; j < 8; j++) {
                    float4 vv = vr[j];
                    o4[j].x = fmaf(p, vv.x, o4[j].x);
                    o4[j].y = fmaf(p, vv.y, o4[j].y);
                    o4[j].z = fmaf(p, vv.z, o4[j].z);
                    o4[j].w = fmaf(p, vv.w, o4[j].w);
                }
            }
            run_max = cmax;
        }
        __syncthreads();
    }

    if (active) {
        float inv = 1.f / run_l;
        float* ob = g_att + (((size_t)b * 256) + h * 32) * 196 + n;
        #pragma unroll
        for (int j = 0; j < 8; j++) {
            ob[(size_t)(4*j + 0) * 196] = hardswish(o4[j].x * inv);
            ob[(size_t)(4*j + 1) * 196] = hardswish(o4[j].y * inv);
            ob[(size_t)(4*j + 2) * 196] = hardswish(o4[j].z * inv);
            ob[(size_t)(4*j + 3) * 196] = hardswish(o4[j].w * inv);
        }
    }
}

// ---------------- launch -----------------------------------------------------
extern "C" void kernel_launch(void* const* d_in, const int* in_sizes, int n_in,
                              void* d_out, int out_size)
{
    const float* x      = (const float*)d_in[0];
    const float* kv_w   = (const float*)d_in[1];
    const float* kv_g   = (const float*)d_in[2];
    const float* kv_b   = (const float*)d_in[3];
    const float* kv_m   = (const float*)d_in[4];
    const float* kv_v   = (const float*)d_in[5];
    const float* q_w    = (const float*)d_in[6];
    const float* q_g    = (const float*)d_in[7];
    const float* q_b    = (const float*)d_in[8];
    const float* q_m    = (const float*)d_in[9];
    const float* q_v    = (const float*)d_in[10];
    const float* proj_w = (const float*)d_in[11];
    const float* proj_g = (const float*)d_in[12];
    const float* proj_b = (const float*)d_in[13];
    const float* proj_m = (const float*)d_in[14];
    const float* proj_v = (const float*)d_in[15];
    const float* ab     = (const float*)d_in[16];
    const int*   idxs   = (const int*)  d_in[17];
    const int n_off = in_sizes[16] / 8;

    float* out = (float*)d_out;

    float *p_kv, *p_q, *p_att;
    cudaGetSymbolAddress((void**)&p_kv,  g_kv);
    cudaGetSymbolAddress((void**)&p_q,   g_q);
    cudaGetSymbolAddress((void**)&p_att, g_att);

    // 1) bias table (transposed for coalesced attention reads)
    bias_gather_kernel<<<dim3(784, 8), 196>>>(ab, idxs, n_off);

    // 2) kv = conv_bn_hsw(x, kv_w)   -> g_kv [64][384][784]
    conv_bn_hsw_tc_kernel<false><<<dim3(3, 13, 64), 256>>>(
        x, 256 * 784, 784, kv_w, 256, kv_g, kv_b, kv_m, kv_v, p_kv, 384, 784);

    // 3) q = conv_bn_hsw(x[::2,::2], q_w) -> g_q [64][128][196]
    conv_bn_hsw_tc_kernel<true><<<dim3(1, 4, 64), 256>>>(
        x, 256 * 784, 784, q_w, 256, q_g, q_b, q_m, q_v, p_q, 128, 196);

    // 4) fused attention (QK^T*scale + bias, softmax, @V, hardswish) -> g_att
    attention_kernel<<<512, 224>>>();

    // 5) proj = conv_bn_hsw(g_att, proj_w) -> d_out [64][512][196]
    conv_bn_hsw_tc_kernel<false><<<dim3(4, 4, 64), 256>>>(
        p_att, 256 * 196, 196, proj_w, 256, proj_g, proj_b, proj_m, proj_v, out, 512, 196);
}

// round 4
// speedup vs baseline: 2.8111x; 1.8255x over previous
#include <cuda_runtime.h>
#include <math.h>
#include <stdint.h>

#define BN_EPS 1e-5f
#define LOG2E 1.4426950408889634f

// ---------------- scratch (static device buffers; no allocations) ----------
__device__ float g_kv  [64u*384u*784u];  // kv conv output  [b][o=384][n=784]
__device__ float g_q   [64u*128u*196u];  // q  conv output  [b][o=128][n=196]
__device__ float g_bias[ 8u*196u*784u];  // bias*log2e  [h][q=196][m=784]
__device__ float g_att [64u*256u*196u];  // hardswish(attn out) [b][c=256][n=196]

__device__ __forceinline__ float hardswish(float x) {
    float t = fminf(fmaxf(x + 3.f, 0.f), 6.f);
    return x * t * (1.f / 6.f);
}

__device__ __forceinline__ uint32_t f2tf32(float x) {
    uint32_t r;
    asm("cvt.rna.tf32.f32 %0, %1;" : "=r"(r) : "f"(x));
    return r;
}

__device__ __forceinline__ void mma_tf32(float c[4], const uint32_t a[4],
                                         uint32_t b0, uint32_t b1) {
    asm volatile(
        "mma.sync.aligned.m16n8k8.row.col.f32.tf32.tf32.f32 "
        "{%0,%1,%2,%3}, {%4,%5,%6,%7}, {%8,%9}, {%0,%1,%2,%3};"
        : "+f"(c[0]), "+f"(c[1]), "+f"(c[2]), "+f"(c[3])
        : "r"(a[0]), "r"(a[1]), "r"(a[2]), "r"(a[3]), "r"(b0), "r"(b1));
}

// ---------------- bias gather: g_bias[h][q][m] = ab[h][idxs[q][m]] * log2e --
__global__ void bias_gather_kernel(const float* __restrict__ ab,
                                   const int*   __restrict__ idxs,
                                   int n_off)
{
    int q = blockIdx.x;       // 0..195
    int h = blockIdx.y;       // 0..7
    int m = threadIdx.x;      // 0..783
    int idx = idxs[q * 784 + m];
    g_bias[((size_t)h * 196 + q) * 784 + m] = ab[h * n_off + idx] * LOG2E;
}

// ---------------- TF32 tensor-core GEMM + BN + hardswish --------------------
template<bool STRIDED>
__global__ void __launch_bounds__(256, 2)
conv_bn_hsw_tc_kernel(const float* __restrict__ X, int x_batch_stride, int ldx,
                      const float* __restrict__ W, int C,
                      const float* __restrict__ gam, const float* __restrict__ bet,
                      const float* __restrict__ mu,  const float* __restrict__ var,
                      float* __restrict__ Y, int O, int Ncols)
{
    __shared__ uint32_t As[128][20];
    __shared__ uint32_t Bs[64][20];

    const int b  = blockIdx.z;
    const float* Xb = X + (size_t)b * x_batch_stride;
    float*       Yb = Y + (size_t)b * O * Ncols;
    const int o0 = blockIdx.x * 128;
    const int n0 = blockIdx.y * 64;
    const int t  = threadIdx.x;

    const int warp = t >> 5;
    const int lane = t & 31;
    const int g    = lane >> 2;
    const int t4   = lane & 3;
    const int wm   = warp >> 2;
    const int wn   = warp & 3;
    const int mrow0 = wm * 64;
    const int ncol0 = wn * 16;

    float acc[4][2][4];
    #pragma unroll
    for (int i = 0; i < 4; i++)
        #pragma unroll
        for (int j = 0; j < 2; j++)
            #pragma unroll
            for (int e = 0; e < 4; e++) acc[i][j][e] = 0.f;

    for (int c0 = 0; c0 < C; c0 += 16) {
        #pragma unroll
        for (int r = 0; r < 2; r++) {
            int q = t + r * 256;
            int row = q >> 2, seg = q & 3;
            float4 av = *reinterpret_cast<const float4*>(&W[(o0 + row) * C + c0 + seg * 4]);
            As[row][seg * 4 + 0] = f2tf32(av.x);
            As[row][seg * 4 + 1] = f2tf32(av.y);
            As[row][seg * 4 + 2] = f2tf32(av.z);
            As[row][seg * 4 + 3] = f2tf32(av.w);
        }
        #pragma unroll
        for (int r = 0; r < 4; r++) {
            int i = t + r * 256;
            int k = i >> 6, n = i & 63;
            int nn = n0 + n;
            float val = 0.f;
            if (nn < Ncols) {
                int gn = STRIDED ? (2 * (nn / 14) * 28 + 2 * (nn % 14)) : nn;
                val = Xb[(size_t)(c0 + k) * ldx + gn];
            }
            Bs[n][k] = f2tf32(val);
        }
        __syncthreads();

        #pragma unroll
        for (int ks = 0; ks < 16; ks += 8) {
            uint32_t a[4][4];
            #pragma unroll
            for (int mf = 0; mf < 4; mf++) {
                int rb = mrow0 + mf * 16;
                a[mf][0] = As[rb + g    ][ks + t4    ];
                a[mf][1] = As[rb + g + 8][ks + t4    ];
                a[mf][2] = As[rb + g    ][ks + t4 + 4];
                a[mf][3] = As[rb + g + 8][ks + t4 + 4];
            }
            uint32_t bfr[2][2];
            #pragma unroll
            for (int nf = 0; nf < 2; nf++) {
                int cb = ncol0 + nf * 8;
                bfr[nf][0] = Bs[cb + g][ks + t4    ];
                bfr[nf][1] = Bs[cb + g][ks + t4 + 4];
            }
            #pragma unroll
            for (int mf = 0; mf < 4; mf++)
                #pragma unroll
                for (int nf = 0; nf < 2; nf++)
                    mma_tf32(acc[mf][nf], a[mf], bfr[nf][0], bfr[nf][1]);
        }
        __syncthreads();
    }

    #pragma unroll
    for (int mf = 0; mf < 4; mf++) {
        #pragma unroll
        for (int half = 0; half < 2; half++) {
            int o = o0 + mrow0 + mf * 16 + g + half * 8;
            float sc = gam[o] * rsqrtf(var[o] + BN_EPS);
            float mm = mu[o], bt = bet[o];
            #pragma unroll
            for (int nf = 0; nf < 2; nf++) {
                #pragma unroll
                for (int e = 0; e < 2; e++) {
                    int n = n0 + ncol0 + nf * 8 + t4 * 2 + e;
                    if (n < Ncols) {
                        float y = (acc[mf][nf][half * 2 + e] - mm) * sc + bt;
                        Yb[(size_t)o * Ncols + n] = hardswish(y);
                    }
                }
            }
        }
    }
}

// ---------------- tensor-core flash attention -------------------------------
// grid (512 bh, 4 qblocks), 128 threads (4 warps, each owns 16 queries).
// key loop: 14 chunks of 56. S via mma (bias preloaded in accumulator),
// online softmax in exp2 domain, P->smem(tf32)->A-frag, PV via mma.
__global__ void __launch_bounds__(128)
attention_tc_kernel()
{
    const int bh = blockIdx.x;
    const int b = bh >> 3, h = bh & 7;
    const int qb = blockIdx.y;
    const int t = threadIdx.x;
    const int warp = t >> 5, lane = t & 31;
    const int g = lane >> 2, t4 = lane & 3;

    __shared__ uint32_t Ks[56 * 20];      // K^T: [m][d] pitch 20 (tf32)
    __shared__ uint32_t Vs[32 * 60];      // V:   [d][m] pitch 60 (tf32)
    __shared__ uint32_t Ps[4][16 * 60];   // per-warp P: [q][m] pitch 60 (tf32)

    const float* kvb  = g_kv   + ((size_t)b * 384 + (size_t)h * 48) * 784;
    const float* bsh  = g_bias + (size_t)h * 196 * 784;

    const int q0 = qb * 64 + warp * 16;
    const int qA = q0 + g, qB = q0 + g + 8;

    // Q fragments (2 k-steps of 8 over d=16), pre-scaled by 0.25*log2e
    uint32_t qa[2][4];
    const float QS = 0.25f * LOG2E;
    #pragma unroll
    for (int ks = 0; ks < 2; ks++) {
        #pragma unroll
        for (int cc = 0; cc < 2; cc++) {
            int d = ks * 8 + t4 + cc * 4;
            float vA = (qA < 196) ? g_q[((size_t)b * 128 + h * 16 + d) * 196 + qA] * QS : 0.f;
            float vB = (qB < 196) ? g_q[((size_t)b * 128 + h * 16 + d) * 196 + qB] * QS : 0.f;
            qa[ks][cc * 2 + 0] = f2tf32(vA);
            qa[ks][cc * 2 + 1] = f2tf32(vB);
        }
    }

    float oc[4][4];
    #pragma unroll
    for (int v = 0; v < 4; v++)
        #pragma unroll
        for (int e = 0; e < 4; e++) oc[v][e] = 0.f;
    float rm0 = -1e30f, rm1 = -1e30f, rl0 = 0.f, rl1 = 0.f;

    for (int m0 = 0; m0 < 784; m0 += 56) {
        // ---- cooperative loads: K transposed, V natural
        #pragma unroll
        for (int i = 0; i < 7; i++) {
            int idx = t + i * 128;               // < 896
            int d = idx / 56, m = idx % 56;
            Ks[m * 20 + d] = f2tf32(kvb[(size_t)d * 784 + m0 + m]);
        }
        #pragma unroll
        for (int i = 0; i < 14; i++) {
            int idx = t + i * 128;               // < 1792
            int d = idx / 56, m = idx % 56;
            Vs[d * 60 + m] = f2tf32(kvb[(size_t)(16 + d) * 784 + m0 + m]);
        }
        __syncthreads();

        // ---- S = bias + Q K^T (bias preloaded into accumulators)
        float sc[7][4];
        #pragma unroll
        for (int j = 0; j < 7; j++) {
            int m = m0 + j * 8 + 2 * t4;
            if (qA < 196) {
                float2 v = *reinterpret_cast<const float2*>(&bsh[(size_t)qA * 784 + m]);
                sc[j][0] = v.x; sc[j][1] = v.y;
            } else { sc[j][0] = 0.f; sc[j][1] = 0.f; }
            if (qB < 196) {
                float2 v = *reinterpret_cast<const float2*>(&bsh[(size_t)qB * 784 + m]);
                sc[j][2] = v.x; sc[j][3] = v.y;
            } else { sc[j][2] = 0.f; sc[j][3] = 0.f; }
        }
        #pragma unroll
        for (int ks = 0; ks < 2; ks++) {
            #pragma unroll
            for (int j = 0; j < 7; j++) {
                uint32_t b0 = Ks[(j * 8 + g) * 20 + ks * 8 + t4];
                uint32_t b1 = Ks[(j * 8 + g) * 20 + ks * 8 + t4 + 4];
                mma_tf32(sc[j], qa[ks], b0, b1);
            }
        }

        // ---- online softmax (exp2 domain)
        float mx0 = rm0, mx1 = rm1;
        #pragma unroll
        for (int j = 0; j < 7; j++) {
            mx0 = fmaxf(mx0, fmaxf(sc[j][0], sc[j][1]));
            mx1 = fmaxf(mx1, fmaxf(sc[j][2], sc[j][3]));
        }
        mx0 = fmaxf(mx0, __shfl_xor_sync(0xffffffffu, mx0, 1));
        mx0 = fmaxf(mx0, __shfl_xor_sync(0xffffffffu, mx0, 2));
        mx1 = fmaxf(mx1, __shfl_xor_sync(0xffffffffu, mx1, 1));
        mx1 = fmaxf(mx1, __shfl_xor_sync(0xffffffffu, mx1, 2));

        float a0 = exp2f(rm0 - mx0), a1 = exp2f(rm1 - mx1);
        rl0 *= a0; rl1 *= a1; rm0 = mx0; rm1 = mx1;
        #pragma unroll
        for (int v = 0; v < 4; v++) {
            oc[v][0] *= a0; oc[v][1] *= a0;
            oc[v][2] *= a1; oc[v][3] *= a1;
        }

        float s0 = 0.f, s1 = 0.f;
        #pragma unroll
        for (int j = 0; j < 7; j++) {
            float p0 = exp2f(sc[j][0] - mx0);
            float p1 = exp2f(sc[j][1] - mx0);
            float p2 = exp2f(sc[j][2] - mx1);
            float p3 = exp2f(sc[j][3] - mx1);
            s0 += p0 + p1; s1 += p2 + p3;
            uint2 lo = make_uint2(f2tf32(p0), f2tf32(p1));
            uint2 hi = make_uint2(f2tf32(p2), f2tf32(p3));
            *reinterpret_cast<uint2*>(&Ps[warp][g * 60 + j * 8 + 2 * t4]) = lo;
            *reinterpret_cast<uint2*>(&Ps[warp][(g + 8) * 60 + j * 8 + 2 * t4]) = hi;
        }
        s0 += __shfl_xor_sync(0xffffffffu, s0, 1);
        s0 += __shfl_xor_sync(0xffffffffu, s0, 2);
        s1 += __shfl_xor_sync(0xffffffffu, s1, 1);
        s1 += __shfl_xor_sync(0xffffffffu, s1, 2);
        rl0 += s0; rl1 += s1;

        __syncwarp();

        // ---- out += P @ V^T
        #pragma unroll
        for (int kk = 0; kk < 7; kk++) {
            uint32_t pa[4];
            pa[0] = Ps[warp][g * 60 + kk * 8 + t4];
            pa[1] = Ps[warp][(g + 8) * 60 + kk * 8 + t4];
            pa[2] = Ps[warp][g * 60 + kk * 8 + t4 + 4];
            pa[3] = Ps[warp][(g + 8) * 60 + kk * 8 + t4 + 4];
            #pragma unroll
            for (int v = 0; v < 4; v++) {
                uint32_t b0 = Vs[(v * 8 + g) * 60 + kk * 8 + t4];
                uint32_t b1 = Vs[(v * 8 + g) * 60 + kk * 8 + t4 + 4];
                mma_tf32(oc[v], pa, b0, b1);
            }
        }
        __syncthreads();
    }

    // ---- normalize, hardswish, store
    float inv0 = 1.f / rl0, inv1 = 1.f / rl1;
    #pragma unroll
    for (int v = 0; v < 4; v++) {
        #pragma unroll
        for (int e = 0; e < 2; e++) {
            int d = v * 8 + 2 * t4 + e;
            if (qA < 196)
                g_att[((size_t)b * 256 + h * 32 + d) * 196 + qA] = hardswish(oc[v][e] * inv0);
            if (qB < 196)
                g_att[((size_t)b * 256 + h * 32 + d) * 196 + qB] = hardswish(oc[v][2 + e] * inv1);
        }
    }
}

// ---------------- launch -----------------------------------------------------
extern "C" void kernel_launch(void* const* d_in, const int* in_sizes, int n_in,
                              void* d_out, int out_size)
{
    const float* x      = (const float*)d_in[0];
    const float* kv_w   = (const float*)d_in[1];
    const float* kv_g   = (const float*)d_in[2];
    const float* kv_b   = (const float*)d_in[3];
    const float* kv_m   = (const float*)d_in[4];
    const float* kv_v   = (const float*)d_in[5];
    const float* q_w    = (const float*)d_in[6];
    const float* q_g    = (const float*)d_in[7];
    const float* q_b    = (const float*)d_in[8];
    const float* q_m    = (const float*)d_in[9];
    const float* q_v    = (const float*)d_in[10];
    const float* proj_w = (const float*)d_in[11];
    const float* proj_g = (const float*)d_in[12];
    const float* proj_b = (const float*)d_in[13];
    const float* proj_m = (const float*)d_in[14];
    const float* proj_v = (const float*)d_in[15];
    const float* ab     = (const float*)d_in[16];
    const int*   idxs   = (const int*)  d_in[17];
    const int n_off = in_sizes[16] / 8;

    float* out = (float*)d_out;

    float *p_kv, *p_q, *p_att;
    cudaGetSymbolAddress((void**)&p_kv,  g_kv);
    cudaGetSymbolAddress((void**)&p_q,   g_q);
    cudaGetSymbolAddress((void**)&p_att, g_att);

    // 1) bias table [h][q][m], *log2e
    bias_gather_kernel<<<dim3(196, 8), 784>>>(ab, idxs, n_off);

    // 2) kv = conv_bn_hsw(x, kv_w)   -> g_kv [64][384][784]
    conv_bn_hsw_tc_kernel<false><<<dim3(3, 13, 64), 256>>>(
        x, 256 * 784, 784, kv_w, 256, kv_g, kv_b, kv_m, kv_v, p_kv, 384, 784);

    // 3) q = conv_bn_hsw(x[::2,::2], q_w) -> g_q [64][128][196]
    conv_bn_hsw_tc_kernel<true><<<dim3(1, 4, 64), 256>>>(
        x, 256 * 784, 784, q_w, 256, q_g, q_b, q_m, q_v, p_q, 128, 196);

    // 4) tensor-core flash attention -> g_att (with pre-proj hardswish)
    attention_tc_kernel<<<dim3(512, 4), 128>>>();

    // 5) proj = conv_bn_hsw(g_att, proj_w) -> d_out [64][512][196]
    conv_bn_hsw_tc_kernel<false><<<dim3(4, 4, 64), 256>>>(
        p_att, 256 * 196, 196, proj_w, 256, proj_g, proj_b, proj_m, proj_v, out, 512, 196);
}

// round 5
// speedup vs baseline: 2.9198x; 1.0387x over previous
#include <cuda_runtime.h>
#include <math.h>
#include <stdint.h>

#define BN_EPS 1e-5f
#define LOG2E 1.4426950408889634f

// ---------------- scratch (static device buffers; no allocations) ----------
__device__ float g_kv  [64u*384u*784u];  // kv conv output  [b][o=384][n=784]
__device__ float g_q   [64u*128u*196u];  // q  conv output  [b][o=128][n=196]
__device__ float g_bias[ 8u*196u*784u];  // bias*log2e  [h][q=196][m=784]
__device__ float g_att [64u*256u*196u];  // hardswish(attn out) [b][c=256][n=196]

__device__ __forceinline__ float hardswish(float x) {
    float t = fminf(fmaxf(x + 3.f, 0.f), 6.f);
    return x * t * (1.f / 6.f);
}

__device__ __forceinline__ uint32_t f2tf32(float x) {
    uint32_t r;
    asm("cvt.rna.tf32.f32 %0, %1;" : "=r"(r) : "f"(x));
    return r;
}

__device__ __forceinline__ void mma_tf32(float c[4], const uint32_t a[4],
                                         uint32_t b0, uint32_t b1) {
    asm volatile(
        "mma.sync.aligned.m16n8k8.row.col.f32.tf32.tf32.f32 "
        "{%0,%1,%2,%3}, {%4,%5,%6,%7}, {%8,%9}, {%0,%1,%2,%3};"
        : "+f"(c[0]), "+f"(c[1]), "+f"(c[2]), "+f"(c[3])
        : "r"(a[0]), "r"(a[1]), "r"(a[2]), "r"(a[3]), "r"(b0), "r"(b1));
}

// ---------------- bias gather: g_bias[h][q][m] = ab[h][idxs[q][m]] * log2e --
__global__ void bias_gather_kernel(const float* __restrict__ ab,
                                   const int*   __restrict__ idxs,
                                   int n_off)
{
    int q = blockIdx.x;       // 0..195
    int h = blockIdx.y;       // 0..7
    int m = threadIdx.x;      // 0..783
    int idx = idxs[q * 784 + m];
    g_bias[((size_t)h * 196 + q) * 784 + m] = ab[h * n_off + idx] * LOG2E;
}

// ---------------- TF32 tensor-core GEMM + BN + hardswish (double-buffered) --
// Y[b][o][n] = hardswish( (sum_c W[o][c]*X[b][c][col(n)] - mu[o])*scale[o]+beta[o] )
// Block 128(O) x 64(N), K-slab 16 pipelined (LDG s+1 | MMA s | STS s+1 | sync).
template<bool STRIDED>
__global__ void __launch_bounds__(256, 2)
conv_bn_hsw_tc_kernel(const float* __restrict__ X, int x_batch_stride, int ldx,
                      const float* __restrict__ W, int C,
                      const float* __restrict__ gam, const float* __restrict__ bet,
                      const float* __restrict__ mu,  const float* __restrict__ var,
                      float* __restrict__ Y, int O, int Ncols)
{
    __shared__ uint32_t As[2][128][20];
    __shared__ uint32_t Bs[2][64][20];

    const int b  = blockIdx.z;
    const float* Xb = X + (size_t)b * x_batch_stride;
    float*       Yb = Y + (size_t)b * O * Ncols;
    const int o0 = blockIdx.x * 128;
    const int n0 = blockIdx.y * 64;
    const int t  = threadIdx.x;

    const int warp = t >> 5;
    const int lane = t & 31;
    const int g    = lane >> 2;
    const int t4   = lane & 3;
    const int wm   = warp >> 2;
    const int wn   = warp & 3;
    const int mrow0 = wm * 64;
    const int ncol0 = wn * 16;

    // loader coordinates (fixed per thread)
    const int arow0 = t >> 2, aseg = t & 3;   // + r*64 rows
    const int bn    = t & 63;                  // B column within tile
    const int bk0   = t >> 6;                  // + r*4 k rows
    int bgn = n0 + bn;
    bool bok = (bgn < Ncols);
    if (STRIDED && bok) bgn = 2 * (bgn / 14) * 28 + 2 * (bgn % 14);

    float acc[4][2][4];
    #pragma unroll
    for (int i = 0; i < 4; i++)
        #pragma unroll
        for (int j = 0; j < 2; j++)
            #pragma unroll
            for (int e = 0; e < 4; e++) acc[i][j][e] = 0.f;

    float4 avr[2];
    float  bvr[4];

    // ---- prologue: load slab 0
    #pragma unroll
    for (int r = 0; r < 2; r++)
        avr[r] = *reinterpret_cast<const float4*>(&W[(o0 + arow0 + r * 64) * C + aseg * 4]);
    #pragma unroll
    for (int r = 0; r < 4; r++)
        bvr[r] = bok ? Xb[(size_t)(bk0 + r * 4) * ldx + bgn] : 0.f;

    int buf = 0;
    #pragma unroll
    for (int r = 0; r < 2; r++) {
        int row = arow0 + r * 64;
        As[0][row][aseg * 4 + 0] = f2tf32(avr[r].x);
        As[0][row][aseg * 4 + 1] = f2tf32(avr[r].y);
        As[0][row][aseg * 4 + 2] = f2tf32(avr[r].z);
        As[0][row][aseg * 4 + 3] = f2tf32(avr[r].w);
    }
    #pragma unroll
    for (int r = 0; r < 4; r++)
        Bs[0][bn][bk0 + r * 4] = f2tf32(bvr[r]);
    __syncthreads();

    const int nslab = C >> 4;
    for (int s = 0; s < nslab; s++) {
        const bool more = (s + 1 < nslab);
        const int c1 = (s + 1) << 4;
        if (more) {
            #pragma unroll
            for (int r = 0; r < 2; r++)
                avr[r] = *reinterpret_cast<const float4*>(
                    &W[(o0 + arow0 + r * 64) * C + c1 + aseg * 4]);
            #pragma unroll
            for (int r = 0; r < 4; r++)
                bvr[r] = bok ? Xb[(size_t)(c1 + bk0 + r * 4) * ldx + bgn] : 0.f;
        }

        // ---- compute slab s from As[buf]/Bs[buf]
        #pragma unroll
        for (int ks = 0; ks < 16; ks += 8) {
            uint32_t a[4][4];
            #pragma unroll
            for (int mf = 0; mf < 4; mf++) {
                int rb = mrow0 + mf * 16;
                a[mf][0] = As[buf][rb + g    ][ks + t4    ];
                a[mf][1] = As[buf][rb + g + 8][ks + t4    ];
                a[mf][2] = As[buf][rb + g    ][ks + t4 + 4];
                a[mf][3] = As[buf][rb + g + 8][ks + t4 + 4];
            }
            uint32_t bfr[2][2];
            #pragma unroll
            for (int nf = 0; nf < 2; nf++) {
                int cb = ncol0 + nf * 8;
                bfr[nf][0] = Bs[buf][cb + g][ks + t4    ];
                bfr[nf][1] = Bs[buf][cb + g][ks + t4 + 4];
            }
            #pragma unroll
            for (int mf = 0; mf < 4; mf++)
                #pragma unroll
                for (int nf = 0; nf < 2; nf++)
                    mma_tf32(acc[mf][nf], a[mf], bfr[nf][0], bfr[nf][1]);
        }

        if (more) {
            int nb = buf ^ 1;
            #pragma unroll
            for (int r = 0; r < 2; r++) {
                int row = arow0 + r * 64;
                As[nb][row][aseg * 4 + 0] = f2tf32(avr[r].x);
                As[nb][row][aseg * 4 + 1] = f2tf32(avr[r].y);
                As[nb][row][aseg * 4 + 2] = f2tf32(avr[r].z);
                As[nb][row][aseg * 4 + 3] = f2tf32(avr[r].w);
            }
            #pragma unroll
            for (int r = 0; r < 4; r++)
                Bs[nb][bn][bk0 + r * 4] = f2tf32(bvr[r]);
        }
        __syncthreads();
        buf ^= 1;
    }

    // ---- epilogue: BN + hardswish
    #pragma unroll
    for (int mf = 0; mf < 4; mf++) {
        #pragma unroll
        for (int half = 0; half < 2; half++) {
            int o = o0 + mrow0 + mf * 16 + g + half * 8;
            float sc = gam[o] * rsqrtf(var[o] + BN_EPS);
            float mm = mu[o], bt = bet[o];
            #pragma unroll
            for (int nf = 0; nf < 2; nf++) {
                #pragma unroll
                for (int e = 0; e < 2; e++) {
                    int n = n0 + ncol0 + nf * 8 + t4 * 2 + e;
                    if (n < Ncols) {
                        float y = (acc[mf][nf][half * 2 + e] - mm) * sc + bt;
                        Yb[(size_t)o * Ncols + n] = hardswish(y);
                    }
                }
            }
        }
    }
}

// ---------------- tensor-core flash attention -------------------------------
// grid (512 bh, 4 qblocks), 128 threads (4 warps, each owns 16 queries).
__global__ void __launch_bounds__(128)
attention_tc_kernel()
{
    const int bh = blockIdx.x;
    const int b = bh >> 3, h = bh & 7;
    const int qb = blockIdx.y;
    const int t = threadIdx.x;
    const int warp = t >> 5, lane = t & 31;
    const int g = lane >> 2, t4 = lane & 3;

    __shared__ uint32_t Ks[56 * 20];      // K^T: [m][d] pitch 20 (tf32)
    __shared__ uint32_t Vs[32 * 60];      // V:   [d][m] pitch 60 (tf32)
    __shared__ uint32_t Ps[4][16 * 60];   // per-warp P: [q][m] pitch 60 (tf32)

    const float* kvb  = g_kv   + ((size_t)b * 384 + (size_t)h * 48) * 784;
    const float* bsh  = g_bias + (size_t)h * 196 * 784;

    // division-free loader coordinates
    const int kd = t >> 3, km = t & 7;    // K: 16 d-rows, m = km + 8j (j<7)
    const int vd = t >> 2, vm = t & 3;    // V: 32 d-rows, m = vm + 4j (j<14)
    const float* kK = kvb + (size_t)kd * 784 + km;
    const float* kV = kvb + (size_t)(16 + vd) * 784 + vm;
    uint32_t* KsT = Ks + km * 20 + kd;
    uint32_t* VsT = Vs + vd * 60 + vm;

    const int q0 = qb * 64 + warp * 16;
    const int qA = q0 + g, qB = q0 + g + 8;

    uint32_t qa[2][4];
    const float QS = 0.25f * LOG2E;
    #pragma unroll
    for (int ks = 0; ks < 2; ks++) {
        #pragma unroll
        for (int cc = 0; cc < 2; cc++) {
            int d = ks * 8 + t4 + cc * 4;
            float vA = (qA < 196) ? g_q[((size_t)b * 128 + h * 16 + d) * 196 + qA] * QS : 0.f;
            float vB = (qB < 196) ? g_q[((size_t)b * 128 + h * 16 + d) * 196 + qB] * QS : 0.f;
            qa[ks][cc * 2 + 0] = f2tf32(vA);
            qa[ks][cc * 2 + 1] = f2tf32(vB);
        }
    }

    float oc[4][4];
    #pragma unroll
    for (int v = 0; v < 4; v++)
        #pragma unroll
        for (int e = 0; e < 4; e++) oc[v][e] = 0.f;
    float rm0 = -1e30f, rm1 = -1e30f, rl0 = 0.f, rl1 = 0.f;

    for (int m0 = 0; m0 < 784; m0 += 56) {
        // ---- cooperative loads (division-free): K transposed, V natural
        #pragma unroll
        for (int j = 0; j < 7; j++)
            KsT[(8 * j) * 20] = f2tf32(kK[m0 + 8 * j]);
        #pragma unroll
        for (int j = 0; j < 14; j++)
            VsT[4 * j] = f2tf32(kV[m0 + 4 * j]);
        __syncthreads();

        // ---- S = bias + Q K^T (bias preloaded into accumulators)
        float sc[7][4];
        #pragma unroll
        for (int j = 0; j < 7; j++) {
            int m = m0 + j * 8 + 2 * t4;
            if (qA < 196) {
                float2 v = *reinterpret_cast<const float2*>(&bsh[(size_t)qA * 784 + m]);
                sc[j][0] = v.x; sc[j][1] = v.y;
            } else { sc[j][0] = 0.f; sc[j][1] = 0.f; }
            if (qB < 196) {
                float2 v = *reinterpret_cast<const float2*>(&bsh[(size_t)qB * 784 + m]);
                sc[j][2] = v.x; sc[j][3] = v.y;
            } else { sc[j][2] = 0.f; sc[j][3] = 0.f; }
        }
        #pragma unroll
        for (int ks = 0; ks < 2; ks++) {
            #pragma unroll
            for (int j = 0; j < 7; j++) {
                uint32_t b0 = Ks[(j * 8 + g) * 20 + ks * 8 + t4];
                uint32_t b1 = Ks[(j * 8 + g) * 20 + ks * 8 + t4 + 4];
                mma_tf32(sc[j], qa[ks], b0, b1);
            }
        }

        // ---- online softmax (exp2 domain)
        float mx0 = rm0, mx1 = rm1;
        #pragma unroll
        for (int j = 0; j < 7; j++) {
            mx0 = fmaxf(mx0, fmaxf(sc[j][0], sc[j][1]));
            mx1 = fmaxf(mx1, fmaxf(sc[j][2], sc[j][3]));
        }
        mx0 = fmaxf(mx0, __shfl_xor_sync(0xffffffffu, mx0, 1));
        mx0 = fmaxf(mx0, __shfl_xor_sync(0xffffffffu, mx0, 2));
        mx1 = fmaxf(mx1, __shfl_xor_sync(0xffffffffu, mx1, 1));
        mx1 = fmaxf(mx1, __shfl_xor_sync(0xffffffffu, mx1, 2));

        float a0 = exp2f(rm0 - mx0), a1 = exp2f(rm1 - mx1);
        rl0 *= a0; rl1 *= a1; rm0 = mx0; rm1 = mx1;
        #pragma unroll
        for (int v = 0; v < 4; v++) {
            oc[v][0] *= a0; oc[v][1] *= a0;
            oc[v][2] *= a1; oc[v][3] *= a1;
        }

        float s0 = 0.f, s1 = 0.f;
        #pragma unroll
        for (int j = 0; j < 7; j++) {
            float p0 = exp2f(sc[j][0] - mx0);
            float p1 = exp2f(sc[j][1] - mx0);
            float p2 = exp2f(sc[j][2] - mx1);
            float p3 = exp2f(sc[j][3] - mx1);
            s0 += p0 + p1; s1 += p2 + p3;
            uint2 lo = make_uint2(f2tf32(p0), f2tf32(p1));
            uint2 hi = make_uint2(f2tf32(p2), f2tf32(p3));
            *reinterpret_cast<uint2*>(&Ps[warp][g * 60 + j * 8 + 2 * t4]) = lo;
            *reinterpret_cast<uint2*>(&Ps[warp][(g + 8) * 60 + j * 8 + 2 * t4]) = hi;
        }
        s0 += __shfl_xor_sync(0xffffffffu, s0, 1);
        s0 += __shfl_xor_sync(0xffffffffu, s0, 2);
        s1 += __shfl_xor_sync(0xffffffffu, s1, 1);
        s1 += __shfl_xor_sync(0xffffffffu, s1, 2);
        rl0 += s0; rl1 += s1;

        __syncwarp();

        // ---- out += P @ V^T
        #pragma unroll
        for (int kk = 0; kk < 7; kk++) {
            uint32_t pa[4];
            pa[0] = Ps[warp][g * 60 + kk * 8 + t4];
            pa[1] = Ps[warp][(g + 8) * 60 + kk * 8 + t4];
            pa[2] = Ps[warp][g * 60 + kk * 8 + t4 + 4];
            pa[3] = Ps[warp][(g + 8) * 60 + kk * 8 + t4 + 4];
            #pragma unroll
            for (int v = 0; v < 4; v++) {
                uint32_t b0 = Vs[(v * 8 + g) * 60 + kk * 8 + t4];
                uint32_t b1 = Vs[(v * 8 + g) * 60 + kk * 8 + t4 + 4];
                mma_tf32(oc[v], pa, b0, b1);
            }
        }
        __syncthreads();
    }

    // ---- normalize, hardswish, store
    float inv0 = 1.f / rl0, inv1 = 1.f / rl1;
    #pragma unroll
    for (int v = 0; v < 4; v++) {
        #pragma unroll
        for (int e = 0; e < 2; e++) {
            int d = v * 8 + 2 * t4 + e;
            if (qA < 196)
                g_att[((size_t)b * 256 + h * 32 + d) * 196 + qA] = hardswish(oc[v][e] * inv0);
            if (qB < 196)
                g_att[((size_t)b * 256 + h * 32 + d) * 196 + qB] = hardswish(oc[v][2 + e] * inv1);
        }
    }
}

// ---------------- launch -----------------------------------------------------
extern "C" void kernel_launch(void* const* d_in, const int* in_sizes, int n_in,
                              void* d_out, int out_size)
{
    const float* x      = (const float*)d_in[0];
    const float* kv_w   = (const float*)d_in[1];
    const float* kv_g   = (const float*)d_in[2];
    const float* kv_b   = (const float*)d_in[3];
    const float* kv_m   = (const float*)d_in[4];
    const float* kv_v   = (const float*)d_in[5];
    const float* q_w    = (const float*)d_in[6];
    const float* q_g    = (const float*)d_in[7];
    const float* q_b    = (const float*)d_in[8];
    const float* q_m    = (const float*)d_in[9];
    const float* q_v    = (const float*)d_in[10];
    const float* proj_w = (const float*)d_in[11];
    const float* proj_g = (const float*)d_in[12];
    const float* proj_b = (const float*)d_in[13];
    const float* proj_m = (const float*)d_in[14];
    const float* proj_v = (const float*)d_in[15];
    const float* ab     = (const float*)d_in[16];
    const int*   idxs   = (const int*)  d_in[17];
    const int n_off = in_sizes[16] / 8;

    float* out = (float*)d_out;

    float *p_kv, *p_q, *p_att;
    cudaGetSymbolAddress((void**)&p_kv,  g_kv);
    cudaGetSymbolAddress((void**)&p_q,   g_q);
    cudaGetSymbolAddress((void**)&p_att, g_att);

    // 1) bias table [h][q][m], *log2e
    bias_gather_kernel<<<dim3(196, 8), 784>>>(ab, idxs, n_off);

    // 2) kv = conv_bn_hsw(x, kv_w)   -> g_kv [64][384][784]
    conv_bn_hsw_tc_kernel<false><<<dim3(3, 13, 64), 256>>>(
        x, 256 * 784, 784, kv_w, 256, kv_g, kv_b, kv_m, kv_v, p_kv, 384, 784);

    // 3) q = conv_bn_hsw(x[::2,::2], q_w) -> g_q [64][128][196]
    conv_bn_hsw_tc_kernel<true><<<dim3(1, 4, 64), 256>>>(
        x, 256 * 784, 784, q_w, 256, q_g, q_b, q_m, q_v, p_q, 128, 196);

    // 4) tensor-core flash attention -> g_att (with pre-proj hardswish)
    attention_tc_kernel<<<dim3(512, 4), 128>>>();

    // 5) proj = conv_bn_hsw(g_att, proj_w) -> d_out [64][512][196]
    conv_bn_hsw_tc_kernel<false><<<dim3(4, 4, 64), 256>>>(
        p_att, 256 * 196, 196, proj_w, 256, proj_g, proj_b, proj_m, proj_v, out, 512, 196);
}